// round 10
// baseline (speedup 1.0000x reference)
#include <cuda_runtime.h>
#include <math.h>

// ---------------- f32x2 packed helpers (sm_103a) ----------------
__device__ __forceinline__ unsigned long long pk2(float lo, float hi) {
    unsigned long long r;
    asm("mov.b64 %0, {%1, %2};" : "=l"(r) : "f"(lo), "f"(hi));
    return r;
}
__device__ __forceinline__ unsigned long long ffma2(unsigned long long a,
                                                    unsigned long long b,
                                                    unsigned long long c) {
    unsigned long long d;
    asm("fma.rn.f32x2 %0, %1, %2, %3;" : "=l"(d) : "l"(a), "l"(b), "l"(c));
    return d;
}
__device__ __forceinline__ float2 upk2(unsigned long long v) {
    float2 f;
    asm("mov.b64 {%0, %1}, %2;" : "=f"(f.x), "=f"(f.y) : "l"(v));
    return f;
}

// ---------------- tf32 mma helpers ----------------
__device__ __forceinline__ unsigned cvt_tf32(float f) {
    unsigned r;
    asm("cvt.rna.tf32.f32 %0, %1;" : "=r"(r) : "f"(f));
    return r;
}
__device__ __forceinline__ void mma_tf32(float* c,
                                         unsigned a0, unsigned a1, unsigned a2, unsigned a3,
                                         unsigned b0, unsigned b1) {
    asm("mma.sync.aligned.m16n8k8.row.col.f32.tf32.tf32.f32 "
        "{%0,%1,%2,%3},{%4,%5,%6,%7},{%8,%9},{%0,%1,%2,%3};"
        : "+f"(c[0]), "+f"(c[1]), "+f"(c[2]), "+f"(c[3])
        : "r"(a0), "r"(a1), "r"(a2), "r"(a3), "r"(b0), "r"(b1));
}

// ---------------- device scratch (static, no allocations) ----------------
__device__ float g_buf1[4096ull * 2880];   // conv1+pool out [N,20,12,12]
__device__ float g_feat[4096ull * 800];    // conv2+pool out flattened [N,800]
__device__ float g_h[4096ull * 50];        // fc out [N,50]
__device__ float g_G[4096ull * 4096];      // gram h h^T
__device__ float g_sq[4096];               // diag of G
__device__ unsigned g_hist[256];
__device__ float g_cuts[256];              // exact squared cutoff per candidate
__device__ float g_cut;                    // dd < g_cut  <=>  sqrt_rn(dd) < thr
__device__ unsigned g_E;
__device__ float g_agg[4096ull * 50];
__device__ float g_deg[4096];
__device__ float g_Z[4096ull * 50];
__device__ float g_colsum[50];
// conv2 weights, tf32, float4-fragment order:
// f: q=f&3, lane=(f>>2)&31, np=(f>>7)&1, nh=(f>>8)&1, ks=f>>9; nt=np*2+(q>>1), pair=q&1
__device__ float g_w2f[63 * 2 * 2 * 32 * 4];
// conv1 weights, tf32, float2-fragment order:
// g_w1f[(ks*3+nt)*64 + lane*2 + pair]; n=nt*8+(lane>>2), k=ks*8+(lane&3)+pair*4
__device__ float g_w1f[768];

// ---------------- prep: hist/cuts init + both weight fragment layouts -------
__global__ void k_prep(const float* __restrict__ w1, const float* __restrict__ w2) {
    int bid = blockIdx.x, tid = threadIdx.x;
    if (bid < 252) {
        int f = bid * 256 + tid;                 // g_w2f: 64512 entries
        int q    = f & 3;
        int lane = (f >> 2) & 31;
        int np   = (f >> 7) & 1;
        int nh   = (f >> 8) & 1;
        int ks   = f >> 9;
        int nt   = np * 2 + (q >> 1);
        int pair = q & 1;
        int n = nh * 32 + nt * 8 + (lane >> 2);
        int k = ks * 8 + (lane & 3) + pair * 4;
        float v = 0.0f;
        if (n < 50 && k < 500) v = __uint_as_float(cvt_tf32(w2[n * 500 + k]));
        g_w2f[f] = v;
    } else {
        // init hist + exact per-candidate squared cutoffs
        g_hist[tid] = 0u;
        float thr = 3.5f + 0.5f * (float)tid;
        float x = thr * thr;
        while (__fsqrt_rn(x) >= thr)
            x = __int_as_float(__float_as_int(x) - 1);
        while (__fsqrt_rn(__int_as_float(__float_as_int(x) + 1)) < thr)
            x = __int_as_float(__float_as_int(x) + 1);
        g_cuts[tid] = __int_as_float(__float_as_int(x) + 1);
        if (tid == 0) g_E = 0u;
        // conv1 weight fragments (768 entries)
        for (int f = tid; f < 768; f += 256) {
            int pair = f & 1;
            int lane = (f >> 1) & 31;
            int rem  = f >> 6;                   // ks*3 + nt, 0..11
            int ks = rem / 3, nt = rem % 3;
            int n = nt * 8 + (lane >> 2);
            int k = ks * 8 + (lane & 3) + pair * 4;
            float v = 0.0f;
            if (n < 20 && k < 25) v = __uint_as_float(cvt_tf32(w1[n * 25 + k]));
            g_w1f[rem * 64 + lane * 2 + pair] = v;
        }
    }
}

// ---------------- conv1 via tf32 tensor-core implicit GEMM ----------------
// Per image: C[576 conv-pos][24 ch-pad] = A[576][32pad im2col] * W^T.
// A gathered from tf32-converted x in smem; K tail -> zero region.
// Epilogue: maxpool 2x2 + bias + relu (relu(max+b) == pool(relu(conv+b))).
__global__ __launch_bounds__(128) void k_conv1(const float* __restrict__ x,
                                               const float* __restrict__ b) {
    extern __shared__ __align__(16) float sm1[];
    int*   s_of = (int*)sm1;            // 32
    float* s_in = sm1 + 32;             // 1456 (784 + zero pad)
    float* s_C  = sm1 + 32 + 1456;      // 576*28
    int img = blockIdx.x, tid = threadIdx.x;
    const float* xin = x + (size_t)img * 784;
    for (int t = tid; t < 784; t += 128)
        s_in[t] = __uint_as_float(cvt_tf32(xin[t]));
    for (int t = 784 + tid; t < 1456; t += 128) s_in[t] = 0.0f;
    if (tid < 32)
        s_of[tid] = (tid < 25) ? ((tid / 5) * 28 + (tid % 5)) : 784;
    __syncthreads();

    int warp = tid >> 5, lane = tid & 31;
    int g = lane >> 2, tg = lane & 3;
    float2 bf[4][3];
    const float2* wf = (const float2*)g_w1f;
    #pragma unroll
    for (int ks = 0; ks < 4; ks++)
        #pragma unroll
        for (int nt = 0; nt < 3; nt++)
            bf[ks][nt] = wf[(ks * 3 + nt) * 32 + lane];
    int o0[4], o1[4];
    #pragma unroll
    for (int ks = 0; ks < 4; ks++) {
        o0[ks] = s_of[ks * 8 + tg];
        o1[ks] = s_of[ks * 8 + tg + 4];
    }
    #pragma unroll 1
    for (int mt = 0; mt < 9; mt++) {
        int tile = warp * 9 + mt;
        int r0 = tile * 16 + g, r1 = r0 + 8;
        int ro0 = (r0 / 24) * 28 + (r0 % 24);
        int ro1 = (r1 / 24) * 28 + (r1 % 24);
        float c[3][4] = {};
        #pragma unroll
        for (int ks = 0; ks < 4; ks++) {
            unsigned a0 = __float_as_uint(s_in[o0[ks] + ro0]);
            unsigned a1 = __float_as_uint(s_in[o0[ks] + ro1]);
            unsigned a2 = __float_as_uint(s_in[o1[ks] + ro0]);
            unsigned a3 = __float_as_uint(s_in[o1[ks] + ro1]);
            #pragma unroll
            for (int nt = 0; nt < 3; nt++)
                mma_tf32(c[nt], a0, a1, a2, a3,
                         __float_as_uint(bf[ks][nt].x), __float_as_uint(bf[ks][nt].y));
        }
        #pragma unroll
        for (int nt = 0; nt < 3; nt++) {
            int nc = nt * 8 + tg * 2;
            s_C[r0 * 28 + nc]     = c[nt][0];
            s_C[r0 * 28 + nc + 1] = c[nt][1];
            s_C[r1 * 28 + nc]     = c[nt][2];
            s_C[r1 * 28 + nc + 1] = c[nt][3];
        }
    }
    __syncthreads();
    for (int idx = tid; idx < 2880; idx += 128) {
        int ch = idx / 144, p = idx % 144;
        int py = p / 12, px = p % 12;
        int oy = py * 2, ox = px * 2;
        float v00 = s_C[(oy * 24 + ox) * 28 + ch];
        float v01 = s_C[(oy * 24 + ox + 1) * 28 + ch];
        float v10 = s_C[((oy + 1) * 24 + ox) * 28 + ch];
        float v11 = s_C[((oy + 1) * 24 + ox + 1) * 28 + ch];
        float m = fmaxf(fmaxf(v00, v01), fmaxf(v10, v11)) + __ldg(&b[ch]);
        g_buf1[(size_t)img * 2880 + idx] = fmaxf(m, 0.0f);
    }
}

// ---------------- conv2 via tf32 tensor-core implicit GEMM, 2 images/CTA -----
__global__ __launch_bounds__(256) void k_conv2(const float* __restrict__ b) {
    extern __shared__ __align__(16) float smc[];
    int2* s_of2 = (int2*)smc;            // 252 int2
    float* s_in = smc + 512;             // [2][2976]
    float* s_C  = smc + 512;             // alias, [2][64*68]
    int img0 = blockIdx.x * 2, tid = threadIdx.x;
    #pragma unroll
    for (int im = 0; im < 2; im++) {
        const float* xin = g_buf1 + (size_t)(img0 + im) * 2880;
        float* si = s_in + im * 2976;
        for (int t = tid; t < 2880; t += 256)
            si[t] = __uint_as_float(cvt_tf32(xin[t]));
        if (tid < 96) si[2880 + tid] = 0.0f;
    }
    for (int t = tid; t < 252; t += 256) {
        int ks = t >> 2, tg = t & 3;
        int k0 = ks * 8 + tg, k1 = k0 + 4;
        int o0 = (k0 < 500) ? ((k0 / 25) * 144 + ((k0 % 25) / 5) * 12 + (k0 % 5)) : 2880;
        int o1 = (k1 < 500) ? ((k1 / 25) * 144 + ((k1 % 25) / 5) * 12 + (k1 % 5)) : 2880;
        s_of2[t] = make_int2(o0, o1);
    }
    __syncthreads();

    int warp = tid >> 5, lane = tid & 31;
    int mt = warp >> 1, nh = warp & 1, nb = nh * 32;
    int g = lane >> 2, tg = lane & 3;
    int r0 = mt * 16 + g, r1 = r0 + 8;
    int ro0 = (r0 >> 3) * 12 + (r0 & 7);
    int ro1 = (r1 >> 3) * 12 + (r1 & 7);

    float c[2][4][4];
    #pragma unroll
    for (int im = 0; im < 2; im++)
        #pragma unroll
        for (int i = 0; i < 4; i++)
            #pragma unroll
            for (int j = 0; j < 4; j++) c[im][i][j] = 0.0f;

    const float4* bp = (const float4*)g_w2f + nh * 64 + lane;
    const int2* ofp = s_of2 + tg;
    #pragma unroll 1
    for (int ks = 0; ks < 63; ks++) {
        float4 b0 = bp[0];
        float4 b1 = bp[32];
        bp += 128;
        int2 oo = ofp[0];
        ofp += 4;
        unsigned a[2][4];
        #pragma unroll
        for (int im = 0; im < 2; im++) {
            const float* si = s_in + im * 2976;
            a[im][0] = __float_as_uint(si[oo.x + ro0]);
            a[im][1] = __float_as_uint(si[oo.x + ro1]);
            a[im][2] = __float_as_uint(si[oo.y + ro0]);
            a[im][3] = __float_as_uint(si[oo.y + ro1]);
        }
        #pragma unroll
        for (int im = 0; im < 2; im++) {
            mma_tf32(c[im][0], a[im][0], a[im][1], a[im][2], a[im][3],
                     __float_as_uint(b0.x), __float_as_uint(b0.y));
            mma_tf32(c[im][1], a[im][0], a[im][1], a[im][2], a[im][3],
                     __float_as_uint(b0.z), __float_as_uint(b0.w));
            mma_tf32(c[im][2], a[im][0], a[im][1], a[im][2], a[im][3],
                     __float_as_uint(b1.x), __float_as_uint(b1.y));
            mma_tf32(c[im][3], a[im][0], a[im][1], a[im][2], a[im][3],
                     __float_as_uint(b1.z), __float_as_uint(b1.w));
        }
    }
    __syncthreads();
    #pragma unroll
    for (int im = 0; im < 2; im++)
        #pragma unroll
        for (int nt = 0; nt < 4; nt++) {
            int nc = nb + nt * 8 + tg * 2;
            float* sc = s_C + im * 4352;
            sc[r0 * 68 + nc]     = c[im][nt][0];
            sc[r0 * 68 + nc + 1] = c[im][nt][1];
            sc[r1 * 68 + nc]     = c[im][nt][2];
            sc[r1 * 68 + nc + 1] = c[im][nt][3];
        }
    __syncthreads();
    if (tid < 200) {
        int ch = tid >> 2, q = tid & 3;
        int qy = q >> 1, qx = q & 1;
        float bias = b[ch];
        #pragma unroll
        for (int im = 0; im < 2; im++) {
            const float* sc = s_C + im * 4352;
            #pragma unroll
            for (int ry = 0; ry < 2; ry++)
                #pragma unroll
                for (int rx = 0; rx < 2; rx++) {
                    int py = qy * 2 + ry, px = qx * 2 + rx;
                    int oy = py * 2, ox = px * 2;
                    float v00 = sc[(oy * 8 + ox) * 68 + ch];
                    float v01 = sc[(oy * 8 + ox + 1) * 68 + ch];
                    float v10 = sc[((oy + 1) * 8 + ox) * 68 + ch];
                    float v11 = sc[((oy + 1) * 8 + ox + 1) * 68 + ch];
                    float m = fmaxf(fmaxf(v00, v01), fmaxf(v10, v11)) + bias;
                    m = fmaxf(m, 0.0f);
                    g_feat[(size_t)(img0 + im) * 800 + ch * 16 + py * 4 + px] = m;
                }
        }
    }
}

// ---------------- fc 800->50 + relu : tiled GEMM, BM=8, vectorized LDS -------
__global__ __launch_bounds__(128) void k_fc(const float* __restrict__ w,
                                            const float* __restrict__ b) {
    __shared__ __align__(16) float s_f[8][36];
    __shared__ __align__(16) float s_w[50][36];
    __shared__ float s_b[50];
    int i0 = blockIdx.x * 8;
    int tid = threadIdx.x;
    if (tid < 50) s_b[tid] = b[tid];
    int r = tid & 7, cq = tid >> 3;
    float acc[4];
    #pragma unroll
    for (int j = 0; j < 4; j++) acc[j] = 0.0f;
    for (int kt = 0; kt < 800; kt += 32) {
        __syncthreads();
        #pragma unroll
        for (int t = tid; t < 256; t += 128) {
            int rr = t >> 5, kk = t & 31;
            s_f[rr][kk] = g_feat[(size_t)(i0 + rr) * 800 + kt + kk];
        }
        #pragma unroll
        for (int t = tid; t < 1600; t += 128) {
            int c = t >> 5, kk = t & 31;
            s_w[c][kk] = w[c * 800 + kt + kk];
        }
        __syncthreads();
        #pragma unroll
        for (int k = 0; k < 32; k += 4) {
            float4 f4 = *(const float4*)&s_f[r][k];
            #pragma unroll
            for (int j = 0; j < 4; j++) {
                int c = cq + 16 * j;
                if (c < 50) {
                    float4 w4 = *(const float4*)&s_w[c][k];
                    acc[j] = fmaf(f4.x, w4.x,
                             fmaf(f4.y, w4.y,
                             fmaf(f4.z, w4.z,
                             fmaf(f4.w, w4.w, acc[j]))));
                }
            }
        }
    }
    #pragma unroll
    for (int j = 0; j < 4; j++) {
        int c = cq + 16 * j;
        if (c < 50)
            g_h[(size_t)(i0 + r) * 50 + c] = fmaxf(acc[j] + s_b[c], 0.0f);
    }
}

// ---------------- gram G = h h^T : symmetric, vectorized, f32x2 -------------
__global__ __launch_bounds__(256) void k_gram() {
    __shared__ __align__(16) float As[50][64];
    __shared__ __align__(16) float Bs[50][64];
    __shared__ __align__(16) float Ts[64][68];
    int bx = blockIdx.x, by = blockIdx.y;
    if (bx < by) return;
    int i0 = by * 64, j0 = bx * 64;
    int tid = threadIdx.x;
    for (int t = tid; t < 64 * 50; t += 256) {
        int r = t / 50, c = t % 50;
        As[c][r] = g_h[(size_t)(i0 + r) * 50 + c];
        Bs[c][r] = g_h[(size_t)(j0 + r) * 50 + c];
    }
    __syncthreads();
    int ty = tid / 16, tx = tid % 16;
    unsigned long long accp[4][2];
    #pragma unroll
    for (int u = 0; u < 4; u++) { accp[u][0] = 0ull; accp[u][1] = 0ull; }
    #pragma unroll 2
    for (int k = 0; k < 50; k++) {
        float4 a4 = *(const float4*)&As[k][ty * 4];
        float4 b4 = *(const float4*)&Bs[k][tx * 4];
        unsigned long long bp0 = pk2(b4.x, b4.y);
        unsigned long long bp1 = pk2(b4.z, b4.w);
        float a[4] = {a4.x, a4.y, a4.z, a4.w};
        #pragma unroll
        for (int u = 0; u < 4; u++) {
            unsigned long long ap = pk2(a[u], a[u]);
            accp[u][0] = ffma2(ap, bp0, accp[u][0]);
            accp[u][1] = ffma2(ap, bp1, accp[u][1]);
        }
    }
    float acc[4][4];
    #pragma unroll
    for (int u = 0; u < 4; u++) {
        float2 lo = upk2(accp[u][0]);
        float2 hi = upk2(accp[u][1]);
        acc[u][0] = lo.x; acc[u][1] = lo.y; acc[u][2] = hi.x; acc[u][3] = hi.y;
    }
    #pragma unroll
    for (int u = 0; u < 4; u++) {
        float4 o = make_float4(acc[u][0], acc[u][1], acc[u][2], acc[u][3]);
        *(float4*)&g_G[(size_t)(i0 + ty * 4 + u) * 4096 + j0 + tx * 4] = o;
    }
    #pragma unroll
    for (int u = 0; u < 4; u++)
        #pragma unroll
        for (int v = 0; v < 4; v++)
            Ts[tx * 4 + v][ty * 4 + u] = acc[u][v];
    __syncthreads();
    {
        int a = tid >> 2;
        int b0 = (tid & 3) * 16;
        #pragma unroll
        for (int q = 0; q < 4; q++) {
            float4 o = *(const float4*)&Ts[a][b0 + q * 4];
            *(float4*)&g_G[(size_t)(j0 + a) * 4096 + i0 + b0 + q * 4] = o;
        }
    }
}

__global__ void k_sq() {
    int i = blockIdx.x * 256 + threadIdx.x;
    if (i < 4096) g_sq[i] = g_G[(size_t)i * 4097];
}

// ---------------- histogram: upper triangle, weight 2, warp-aggregated ------
__global__ __launch_bounds__(256) void k_hist() {
    __shared__ unsigned s_hist[256];
    __shared__ float cuts_s[256];
    int tid = threadIdx.x;
    s_hist[tid] = 0u;
    cuts_s[tid] = g_cuts[tid];
    __syncthreads();
    int i = blockIdx.x;
    float sqi = g_sq[i];
    const float* Grow = g_G + (size_t)i * 4096;
    int lane = tid & 31;
    int jb0 = ((i + 1) >> 8) << 8;
    for (int jb = jb0; jb < 4096; jb += 256) {
        int j = jb + tid;
        bool valid = (j > i);
        int b0 = 0x7fffffff;
        if (valid) {
            float g = Grow[j];
            float dd = fmaxf(sqi - 2.0f * g + g_sq[j], 0.0f);
            int lo = 0, hi = 256;
            #pragma unroll
            for (int s = 0; s < 8; s++) {
                int mid = (lo + hi) >> 1;
                if (dd < cuts_s[mid]) hi = mid; else lo = mid + 1;
            }
            b0 = lo;
            if (b0 >= 256) { b0 = 0x7fffffff; valid = false; }
        }
        unsigned m = __match_any_sync(0xffffffffu, b0);
        if (valid) {
            int leader = __ffs(m) - 1;
            if (lane == leader)
                atomicAdd(&s_hist[b0], 2u * (unsigned)__popc(m));
        }
    }
    __syncthreads();
    unsigned v = s_hist[tid];
    if (v) atomicAdd(&g_hist[tid], v);
}

// ---------------- prefix scan -> pick squared-distance cutoff ----------------
__global__ void k_scan() {
    __shared__ unsigned s_h[256];
    __shared__ int s_min;
    int k = threadIdx.x;
    s_h[k] = g_hist[k];
    if (k == 0) s_min = 256;
    __syncthreads();
    unsigned cnt = 0;
    for (int b = 0; b <= k; b++) cnt += s_h[b];
    if ((float)cnt >= 409.6f) atomicMin(&s_min, k);  // 0.1 * 4096
    __syncthreads();
    if (k == 0) {
        int kk = (s_min >= 256) ? 0 : s_min;
        g_cut = g_cuts[kk];
    }
}

// ---------------- dense agg = A @ h, deg, E (mask from G, no atomics) --------
__global__ __launch_bounds__(256) void k_agg() {
    __shared__ float h_s[128][51];
    __shared__ float sq_s[128];
    __shared__ float G_s[32][129];
    __shared__ unsigned s_E;
    int tid = threadIdx.x;
    if (tid == 0) s_E = 0u;
    int r = tid >> 3;
    int tx = tid & 7;
    int i = blockIdx.x * 32 + r;
    float cut = g_cut;
    float sqi = g_sq[i];
    float acc[7];
    #pragma unroll
    for (int u = 0; u < 7; u++) acc[u] = 0.0f;
    int deg = 0;
    for (int jt = 0; jt < 4096; jt += 128) {
        __syncthreads();
        for (int t = tid; t < 128 * 50; t += 256) {
            int rr = t / 50, c = t % 50;
            h_s[rr][c] = g_h[(size_t)(jt + rr) * 50 + c];
        }
        if (tid < 128) sq_s[tid] = g_sq[jt + tid];
        for (int t = tid; t < 32 * 128; t += 256) {
            int rr = t >> 7, jj = t & 127;
            G_s[rr][jj] = g_G[(size_t)(blockIdx.x * 32 + rr) * 4096 + jt + jj];
        }
        __syncthreads();
        #pragma unroll 4
        for (int jj = 0; jj < 128; jj++) {
            float g = G_s[r][jj];
            float dd = fmaxf(sqi - 2.0f * g + sq_s[jj], 0.0f);
            if (dd < cut && (jt + jj) != i) {
                deg++;
                #pragma unroll
                for (int u = 0; u < 7; u++) {
                    int c = tx + 8 * u;
                    if (c < 50) acc[u] += h_s[jj][c];
                }
            }
        }
    }
    #pragma unroll
    for (int u = 0; u < 7; u++) {
        int c = tx + 8 * u;
        if (c < 50) g_agg[(size_t)i * 50 + c] = acc[u];
    }
    if (tx == 0) {
        g_deg[i] = (float)deg;
        atomicAdd(&s_E, (unsigned)deg);
    }
    __syncthreads();
    if (tid == 0 && s_E) atomicAdd(&g_E, s_E);
}

// ---------------- Z = leaky((agg/deg) Wrel^T + brel + h Wroot^T) -------------
__global__ __launch_bounds__(256) void k_z(const float* __restrict__ wrel,
                                           const float* __restrict__ brel,
                                           const float* __restrict__ wroot) {
    __shared__ float s_m[16][52];
    __shared__ float s_h[16][52];
    __shared__ float w1t[50][52];
    __shared__ float w2t[50][52];
    __shared__ float s_b[50];
    int i0 = blockIdx.x * 16;
    int tid = threadIdx.x;
    if (tid < 50) s_b[tid] = brel[tid];
    for (int t = tid; t < 2500; t += 256) {
        int o = t / 50, c = t % 50;
        w1t[c][o] = wrel[t];
        w2t[c][o] = wroot[t];
    }
    for (int t = tid; t < 800; t += 256) {
        int r = t / 50, c = t % 50;
        float dg = fmaxf(g_deg[i0 + r], 1.0f);
        s_m[r][c] = g_agg[(size_t)(i0 + r) * 50 + c] / dg;
        s_h[r][c] = g_h[(size_t)(i0 + r) * 50 + c];
    }
    __syncthreads();
    for (int t = tid; t < 800; t += 256) {
        int r = t / 50, o = t % 50;
        float a = s_b[o];
        #pragma unroll
        for (int c = 0; c < 50; c++)
            a = fmaf(s_m[r][c], w1t[c][o], fmaf(s_h[r][c], w2t[c][o], a));
        float z = (a >= 0.0f) ? a : 0.01f * a;
        g_Z[(size_t)(i0 + r) * 50 + o] = z;
    }
}

// ---------------- column sums of Z (softmax over size-1 axis == ones) --------
__global__ __launch_bounds__(256) void k_colsum() {
    __shared__ float red[256];
    int c = blockIdx.x, tid = threadIdx.x;
    float s = 0.0f;
    for (int i = tid; i < 4096; i += 256) s += g_Z[(size_t)i * 50 + c];
    red[tid] = s;
    __syncthreads();
    for (int w = 128; w > 0; w >>= 1) {
        if (tid < w) red[tid] += red[tid + w];
        __syncthreads();
    }
    if (tid == 0) g_colsum[c] = red[0];
}

// ---------------- final head ----------------
__global__ void k_final(const float* __restrict__ wrel, const float* __restrict__ brel,
                        const float* __restrict__ wroot,
                        const float* __restrict__ l1w, const float* __restrict__ l1b,
                        const float* __restrict__ l2w, const float* __restrict__ l2b,
                        float* __restrict__ out, int out_size) {
    __shared__ float xp0[50];
    __shared__ float xp[50];
    __shared__ float v1[25];
    int tid = threadIdx.x;
    if (tid < 50) xp0[tid] = g_colsum[tid];
    __syncthreads();
    float Ef = (float)g_E;
    float degv = fmaxf(Ef, 1.0f);
    if (tid < 50) {
        float a = brel[tid];
        for (int c = 0; c < 50; c++) {
            float m = (Ef * xp0[c]) / degv;
            a = fmaf(m, wrel[tid * 50 + c], fmaf(xp0[c], wroot[tid * 50 + c], a));
        }
        xp[tid] = (a >= 0.0f) ? a : 0.01f * a;
    }
    __syncthreads();
    if (tid < 25) {
        float a = l1b[tid];
        for (int c = 0; c < 50; c++) a = fmaf(xp[c], l1w[tid * 50 + c], a);
        v1[tid] = (a >= 0.0f) ? a : 0.01f * a;
    }
    __syncthreads();
    if (tid == 0) {
        float v2[2];
        for (int k = 0; k < 2; k++) {
            float a = l2b[k];
            for (int c = 0; c < 25; c++) a = fmaf(v1[c], l2w[k * 25 + c], a);
            v2[k] = (a >= 0.0f) ? a : 0.01f * a;
        }
        float mx = fmaxf(v2[0], v2[1]);
        float e0 = expf(v2[0] - mx), e1 = expf(v2[1] - mx);
        float inv = 1.0f / (e0 + e1);
        float p0 = e0 * inv, p1 = e1 * inv;
        int am = (p1 > p0) ? 1 : 0;
        float pm = fmaxf(p0, p1);
        unsigned E = g_E;
        float l1 = sqrtf((float)(16777216u - E)) / 16777216.0f;
        if (out_size > 0) out[0] = pm;
        if (out_size > 1) out[1] = (float)am;
        if (out_size > 2) out[2] = l1;
    }
}

// ---------------- launch ----------------
extern "C" void kernel_launch(void* const* d_in, const int* in_sizes, int n_in,
                              void* d_out, int out_size) {
    (void)in_sizes; (void)n_in;
    const float* x        = (const float*)d_in[0];
    const float* conv1_w  = (const float*)d_in[1];
    const float* conv1_b  = (const float*)d_in[2];
    const float* conv2_w  = (const float*)d_in[3];
    const float* conv2_b  = (const float*)d_in[4];
    const float* fc_w     = (const float*)d_in[5];
    const float* fc_b     = (const float*)d_in[6];
    const float* erel_w   = (const float*)d_in[7];
    const float* erel_b   = (const float*)d_in[8];
    const float* eroot_w  = (const float*)d_in[9];
    // d_in[10..14]: pool_* / mlp_* — dead (softmax over size-1 axis == 1)
    const float* lin1_w   = (const float*)d_in[15];
    const float* lin1_b   = (const float*)d_in[16];
    const float* lin2_w   = (const float*)d_in[17];
    const float* lin2_b   = (const float*)d_in[18];
    float* out = (float*)d_out;

    const int SMEM1 = (32 + 1456 + 576 * 28) * 4;   // 70464 B
    const int SMEM2 = (512 + 2 * 4352) * 4;         // 36928 B
    cudaFuncSetAttribute(k_conv1, cudaFuncAttributeMaxDynamicSharedMemorySize, SMEM1);

    k_prep<<<253, 256>>>(conv1_w, conv2_w);
    k_conv1<<<4096, 128, SMEM1>>>(x, conv1_b);
    k_conv2<<<2048, 256, SMEM2>>>(conv2_b);
    k_fc<<<512, 128>>>(fc_w, fc_b);
    k_gram<<<dim3(64, 64), 256>>>();
    k_sq<<<16, 256>>>();
    k_hist<<<4096, 256>>>();
    k_scan<<<1, 256>>>();
    k_agg<<<128, 256>>>();
    k_z<<<256, 256>>>(erel_w, erel_b, eroot_w);
    k_colsum<<<50, 256>>>();
    k_final<<<1, 64>>>(erel_w, erel_b, eroot_w, lin1_w, lin1_b, lin2_w, lin2_b, out, out_size);
}

// round 12
// speedup vs baseline: 1.0475x; 1.0475x over previous
#include <cuda_runtime.h>
#include <math.h>

// ---------------- f32x2 packed helpers (sm_103a) ----------------
__device__ __forceinline__ unsigned long long pk2(float lo, float hi) {
    unsigned long long r;
    asm("mov.b64 %0, {%1, %2};" : "=l"(r) : "f"(lo), "f"(hi));
    return r;
}
__device__ __forceinline__ unsigned long long ffma2(unsigned long long a,
                                                    unsigned long long b,
                                                    unsigned long long c) {
    unsigned long long d;
    asm("fma.rn.f32x2 %0, %1, %2, %3;" : "=l"(d) : "l"(a), "l"(b), "l"(c));
    return d;
}
__device__ __forceinline__ float2 upk2(unsigned long long v) {
    float2 f;
    asm("mov.b64 {%0, %1}, %2;" : "=f"(f.x), "=f"(f.y) : "l"(v));
    return f;
}

// ---------------- tf32 mma helpers ----------------
__device__ __forceinline__ unsigned cvt_tf32(float f) {
    unsigned r;
    asm("cvt.rna.tf32.f32 %0, %1;" : "=r"(r) : "f"(f));
    return r;
}
__device__ __forceinline__ void mma_tf32(float* c,
                                         unsigned a0, unsigned a1, unsigned a2, unsigned a3,
                                         unsigned b0, unsigned b1) {
    asm("mma.sync.aligned.m16n8k8.row.col.f32.tf32.tf32.f32 "
        "{%0,%1,%2,%3},{%4,%5,%6,%7},{%8,%9},{%0,%1,%2,%3};"
        : "+f"(c[0]), "+f"(c[1]), "+f"(c[2]), "+f"(c[3])
        : "r"(a0), "r"(a1), "r"(a2), "r"(a3), "r"(b0), "r"(b1));
}

// ---------------- device scratch (static, no allocations) ----------------
__device__ float g_buf1[4096ull * 2880];   // conv1+pool out [N,20,12,12]
__device__ float g_feat[4096ull * 800];    // conv2+pool out flattened [N,800]
__device__ float g_h[4096ull * 50];        // fc out [N,50]
__device__ float g_G[4096ull * 4096];      // gram h h^T
__device__ float g_sq[4096];               // ||h_i||^2
__device__ unsigned g_hist[256];
__device__ float g_cuts[256];              // exact squared cutoff per candidate
__device__ float g_cut;                    // dd < g_cut  <=>  sqrt_rn(dd) < thr
__device__ unsigned g_E;
__device__ float g_agg[4096ull * 50];
__device__ float g_deg[4096];
__device__ float g_Z[4096ull * 50];
__device__ float g_colsum[50];
// conv2 weights, tf32, float4-fragment order (ks=63):
__device__ float g_w2f[63 * 2 * 2 * 32 * 4];

// ---------------- prep: hist/cuts init + conv2 fragment weights -------------
__global__ void k_prep(const float* __restrict__ w2) {
    int bid = blockIdx.x, tid = threadIdx.x;
    if (bid < 252) {
        int f = bid * 256 + tid;                 // g_w2f: 64512 entries
        int q    = f & 3;
        int lane = (f >> 2) & 31;
        int np   = (f >> 7) & 1;
        int nh   = (f >> 8) & 1;
        int ks   = f >> 9;
        int nt   = np * 2 + (q >> 1);
        int pair = q & 1;
        int n = nh * 32 + nt * 8 + (lane >> 2);
        int k = ks * 8 + (lane & 3) + pair * 4;
        float v = 0.0f;
        if (n < 50 && k < 500) v = __uint_as_float(cvt_tf32(w2[n * 500 + k]));
        g_w2f[f] = v;
    } else {
        g_hist[tid] = 0u;
        float thr = 3.5f + 0.5f * (float)tid;
        float x = thr * thr;
        while (__fsqrt_rn(x) >= thr)
            x = __int_as_float(__float_as_int(x) - 1);
        while (__fsqrt_rn(__int_as_float(__float_as_int(x) + 1)) < thr)
            x = __int_as_float(__float_as_int(x) + 1);
        g_cuts[tid] = __int_as_float(__float_as_int(x) + 1);
        if (tid == 0) g_E = 0u;
    }
}

// ---------------- conv1 (1->20, 5x5 VALID) + relu + maxpool2, scalar f32x2 ---
__global__ __launch_bounds__(256) void k_conv1(const float* __restrict__ x,
                                               const float* __restrict__ w,
                                               const float* __restrict__ b) {
    __shared__ __align__(16) float s_in[784];
    __shared__ float s_w[500];
    __shared__ float s_b[20];
    int img = blockIdx.x;
    int tid = threadIdx.x;
    const float* xin = x + (size_t)img * 784;
    for (int t = tid; t < 784; t += 256) s_in[t] = xin[t];
    for (int t = tid; t < 500; t += 256) s_w[t] = w[t];
    if (tid < 20) s_b[tid] = b[tid];
    __syncthreads();
    #pragma unroll 1
    for (int idx = tid; idx < 20 * 36; idx += 256) {
        int c = idx / 36;
        int q = idx % 36;
        int qy = q / 6, qx = q % 6;
        int y0 = qy * 4, x0 = qx * 4;
        unsigned long long wp[25];
        #pragma unroll
        for (int k = 0; k < 25; k++) { float wv = s_w[c * 25 + k]; wp[k] = pk2(wv, wv); }
        unsigned long long acc[4][2];
        {
            unsigned long long bp = pk2(s_b[c], s_b[c]);
            #pragma unroll
            for (int oy = 0; oy < 4; oy++) { acc[oy][0] = bp; acc[oy][1] = bp; }
        }
        const float* ib = &s_in[y0 * 28 + x0];
        #pragma unroll
        for (int r = 0; r < 8; r++) {
            float rv[8];
            #pragma unroll
            for (int t2 = 0; t2 < 4; t2++) {
                float2 v = *(const float2*)&ib[r * 28 + t2 * 2];
                rv[2 * t2] = v.x; rv[2 * t2 + 1] = v.y;
            }
            unsigned long long p[7];
            #pragma unroll
            for (int t2 = 0; t2 < 7; t2++) p[t2] = pk2(rv[t2], rv[t2 + 1]);
            #pragma unroll
            for (int ky = 0; ky < 5; ky++) {
                int oy = r - ky;
                if (oy >= 0 && oy < 4) {
                    #pragma unroll
                    for (int kx = 0; kx < 5; kx++) {
                        acc[oy][0] = ffma2(p[kx],     wp[ky * 5 + kx], acc[oy][0]);
                        acc[oy][1] = ffma2(p[kx + 2], wp[ky * 5 + kx], acc[oy][1]);
                    }
                }
            }
        }
        float o[4][4];
        #pragma unroll
        for (int oy = 0; oy < 4; oy++) {
            float2 lo = upk2(acc[oy][0]);
            float2 hi = upk2(acc[oy][1]);
            o[oy][0] = lo.x; o[oy][1] = lo.y; o[oy][2] = hi.x; o[oy][3] = hi.y;
        }
        #pragma unroll
        for (int ry = 0; ry < 2; ry++)
            #pragma unroll
            for (int rx = 0; rx < 2; rx++) {
                float m = fmaxf(fmaxf(o[2*ry][2*rx], o[2*ry][2*rx+1]),
                                fmaxf(o[2*ry+1][2*rx], o[2*ry+1][2*rx+1]));
                m = fmaxf(m, 0.0f);
                int py = qy * 2 + ry, px = qx * 2 + rx;
                g_buf1[(size_t)img * 2880 + c * 144 + py * 12 + px] = m;
            }
    }
}

// ---------------- conv2 via tf32 tensor-core implicit GEMM, 2 images/CTA -----
__global__ __launch_bounds__(256) void k_conv2(const float* __restrict__ b) {
    extern __shared__ __align__(16) float smc[];
    int2* s_of2 = (int2*)smc;            // 252 int2
    float* s_in = smc + 512;             // [2][2976]
    float* s_C  = smc + 512;             // alias, [2][64*68]
    int img0 = blockIdx.x * 2, tid = threadIdx.x;
    #pragma unroll
    for (int im = 0; im < 2; im++) {
        const float* xin = g_buf1 + (size_t)(img0 + im) * 2880;
        float* si = s_in + im * 2976;
        for (int t = tid; t < 2880; t += 256)
            si[t] = __uint_as_float(cvt_tf32(xin[t]));
        if (tid < 96) si[2880 + tid] = 0.0f;
    }
    for (int t = tid; t < 252; t += 256) {
        int ks = t >> 2, tg = t & 3;
        int k0 = ks * 8 + tg, k1 = k0 + 4;
        int o0 = (k0 < 500) ? ((k0 / 25) * 144 + ((k0 % 25) / 5) * 12 + (k0 % 5)) : 2880;
        int o1 = (k1 < 500) ? ((k1 / 25) * 144 + ((k1 % 25) / 5) * 12 + (k1 % 5)) : 2880;
        s_of2[t] = make_int2(o0, o1);
    }
    __syncthreads();

    int warp = tid >> 5, lane = tid & 31;
    int mt = warp >> 1, nh = warp & 1, nb = nh * 32;
    int g = lane >> 2, tg = lane & 3;
    int r0 = mt * 16 + g, r1 = r0 + 8;
    int ro0 = (r0 >> 3) * 12 + (r0 & 7);
    int ro1 = (r1 >> 3) * 12 + (r1 & 7);

    float c[2][4][4];
    #pragma unroll
    for (int im = 0; im < 2; im++)
        #pragma unroll
        for (int i = 0; i < 4; i++)
            #pragma unroll
            for (int j = 0; j < 4; j++) c[im][i][j] = 0.0f;

    const float4* bp = (const float4*)g_w2f + nh * 64 + lane;
    const int2* ofp = s_of2 + tg;
    #pragma unroll 1
    for (int ks = 0; ks < 63; ks++) {
        float4 b0 = bp[0];
        float4 b1 = bp[32];
        bp += 128;
        int2 oo = ofp[0];
        ofp += 4;
        unsigned a[2][4];
        #pragma unroll
        for (int im = 0; im < 2; im++) {
            const float* si = s_in + im * 2976;
            a[im][0] = __float_as_uint(si[oo.x + ro0]);
            a[im][1] = __float_as_uint(si[oo.x + ro1]);
            a[im][2] = __float_as_uint(si[oo.y + ro0]);
            a[im][3] = __float_as_uint(si[oo.y + ro1]);
        }
        #pragma unroll
        for (int im = 0; im < 2; im++) {
            mma_tf32(c[im][0], a[im][0], a[im][1], a[im][2], a[im][3],
                     __float_as_uint(b0.x), __float_as_uint(b0.y));
            mma_tf32(c[im][1], a[im][0], a[im][1], a[im][2], a[im][3],
                     __float_as_uint(b0.z), __float_as_uint(b0.w));
            mma_tf32(c[im][2], a[im][0], a[im][1], a[im][2], a[im][3],
                     __float_as_uint(b1.x), __float_as_uint(b1.y));
            mma_tf32(c[im][3], a[im][0], a[im][1], a[im][2], a[im][3],
                     __float_as_uint(b1.z), __float_as_uint(b1.w));
        }
    }
    __syncthreads();
    #pragma unroll
    for (int im = 0; im < 2; im++)
        #pragma unroll
        for (int nt = 0; nt < 4; nt++) {
            int nc = nb + nt * 8 + tg * 2;
            float* sc = s_C + im * 4352;
            sc[r0 * 68 + nc]     = c[im][nt][0];
            sc[r0 * 68 + nc + 1] = c[im][nt][1];
            sc[r1 * 68 + nc]     = c[im][nt][2];
            sc[r1 * 68 + nc + 1] = c[im][nt][3];
        }
    __syncthreads();
    if (tid < 200) {
        int ch = tid >> 2, q = tid & 3;
        int qy = q >> 1, qx = q & 1;
        float bias = b[ch];
        #pragma unroll
        for (int im = 0; im < 2; im++) {
            const float* sc = s_C + im * 4352;
            #pragma unroll
            for (int ry = 0; ry < 2; ry++)
                #pragma unroll
                for (int rx = 0; rx < 2; rx++) {
                    int py = qy * 2 + ry, px = qx * 2 + rx;
                    int oy = py * 2, ox = px * 2;
                    float v00 = sc[(oy * 8 + ox) * 68 + ch];
                    float v01 = sc[(oy * 8 + ox + 1) * 68 + ch];
                    float v10 = sc[((oy + 1) * 8 + ox) * 68 + ch];
                    float v11 = sc[((oy + 1) * 8 + ox + 1) * 68 + ch];
                    float m = fmaxf(fmaxf(v00, v01), fmaxf(v10, v11)) + bias;
                    m = fmaxf(m, 0.0f);
                    g_feat[(size_t)(img0 + im) * 800 + ch * 16 + py * 4 + px] = m;
                }
        }
    }
}

// ---------------- fc 800->50 + relu : tiled GEMM, BM=8, vectorized LDS -------
__global__ __launch_bounds__(128) void k_fc(const float* __restrict__ w,
                                            const float* __restrict__ b) {
    __shared__ __align__(16) float s_f[8][36];
    __shared__ __align__(16) float s_w[50][36];
    __shared__ float s_b[50];
    int i0 = blockIdx.x * 8;
    int tid = threadIdx.x;
    if (tid < 50) s_b[tid] = b[tid];
    int r = tid & 7, cq = tid >> 3;
    float acc[4];
    #pragma unroll
    for (int j = 0; j < 4; j++) acc[j] = 0.0f;
    for (int kt = 0; kt < 800; kt += 32) {
        __syncthreads();
        #pragma unroll
        for (int t = tid; t < 256; t += 128) {
            int rr = t >> 5, kk = t & 31;
            s_f[rr][kk] = g_feat[(size_t)(i0 + rr) * 800 + kt + kk];
        }
        #pragma unroll
        for (int t = tid; t < 1600; t += 128) {
            int c = t >> 5, kk = t & 31;
            s_w[c][kk] = w[c * 800 + kt + kk];
        }
        __syncthreads();
        #pragma unroll
        for (int k = 0; k < 32; k += 4) {
            float4 f4 = *(const float4*)&s_f[r][k];
            #pragma unroll
            for (int j = 0; j < 4; j++) {
                int c = cq + 16 * j;
                if (c < 50) {
                    float4 w4 = *(const float4*)&s_w[c][k];
                    acc[j] = fmaf(f4.x, w4.x,
                             fmaf(f4.y, w4.y,
                             fmaf(f4.z, w4.z,
                             fmaf(f4.w, w4.w, acc[j]))));
                }
            }
        }
    }
    #pragma unroll
    for (int j = 0; j < 4; j++) {
        int c = cq + 16 * j;
        if (c < 50)
            g_h[(size_t)(i0 + r) * 50 + c] = fmaxf(acc[j] + s_b[c], 0.0f);
    }
}

// ---------------- sq[i] = ||h_i||^2 (needed by gram's fused binning) ---------
__global__ void k_sq() {
    int i = blockIdx.x * 256 + threadIdx.x;
    if (i < 4096) {
        const float* hr = g_h + (size_t)i * 50;
        float a = 0.0f;
        #pragma unroll
        for (int k = 0; k < 50; k++) a = fmaf(hr[k], hr[k], a);
        g_sq[i] = a;
    }
}

// ---------------- gram G = h h^T + fused distance histogram -----------------
// Upper-triangle block pairs only; mirror stored via smem transpose.
// While the 64x64 tile is in registers, bin dd = sq_i - 2g + sq_j into the
// 256-candidate histogram (j > i only, weight 2) — replaces the k_hist pass.
__global__ __launch_bounds__(256) void k_gram() {
    __shared__ __align__(16) float As[50][64];
    __shared__ __align__(16) float Bs[50][64];
    __shared__ __align__(16) float Ts[64][68];
    __shared__ float cuts_s[256];
    __shared__ unsigned s_hist[256];
    __shared__ float sqA[64], sqB[64];
    int bx = blockIdx.x, by = blockIdx.y;
    if (bx < by) return;
    int i0 = by * 64, j0 = bx * 64;
    int tid = threadIdx.x;
    cuts_s[tid] = g_cuts[tid];
    s_hist[tid] = 0u;
    if (tid < 64) sqA[tid] = g_sq[i0 + tid];
    else if (tid < 128) sqB[tid - 64] = g_sq[j0 + tid - 64];
    for (int t = tid; t < 64 * 50; t += 256) {
        int r = t / 50, c = t % 50;
        As[c][r] = g_h[(size_t)(i0 + r) * 50 + c];
        Bs[c][r] = g_h[(size_t)(j0 + r) * 50 + c];
    }
    __syncthreads();
    int ty = tid / 16, tx = tid % 16;
    int lane = tid & 31;
    unsigned long long accp[4][2];
    #pragma unroll
    for (int u = 0; u < 4; u++) { accp[u][0] = 0ull; accp[u][1] = 0ull; }
    #pragma unroll 2
    for (int k = 0; k < 50; k++) {
        float4 a4 = *(const float4*)&As[k][ty * 4];
        float4 b4 = *(const float4*)&Bs[k][tx * 4];
        unsigned long long bp0 = pk2(b4.x, b4.y);
        unsigned long long bp1 = pk2(b4.z, b4.w);
        float a[4] = {a4.x, a4.y, a4.z, a4.w};
        #pragma unroll
        for (int u = 0; u < 4; u++) {
            unsigned long long ap = pk2(a[u], a[u]);
            accp[u][0] = ffma2(ap, bp0, accp[u][0]);
            accp[u][1] = ffma2(ap, bp1, accp[u][1]);
        }
    }
    float acc[4][4];
    #pragma unroll
    for (int u = 0; u < 4; u++) {
        float2 lo = upk2(accp[u][0]);
        float2 hi = upk2(accp[u][1]);
        acc[u][0] = lo.x; acc[u][1] = lo.y; acc[u][2] = hi.x; acc[u][3] = hi.y;
    }
    // fused binning (same semantics as the old k_hist: j > i, weight 2)
    #pragma unroll
    for (int u = 0; u < 4; u++) {
        #pragma unroll
        for (int v = 0; v < 4; v++) {
            int i = i0 + ty * 4 + u, j = j0 + tx * 4 + v;
            bool valid = (j > i);
            int b0 = 0x7fffffff;
            if (valid) {
                float dd = fmaxf(sqA[ty * 4 + u] - 2.0f * acc[u][v] + sqB[tx * 4 + v], 0.0f);
                int lo = 0, hi = 256;
                #pragma unroll
                for (int s = 0; s < 8; s++) {
                    int mid = (lo + hi) >> 1;
                    if (dd < cuts_s[mid]) hi = mid; else lo = mid + 1;
                }
                b0 = lo;
                if (b0 >= 256) { b0 = 0x7fffffff; valid = false; }
            }
            unsigned m = __match_any_sync(0xffffffffu, b0);
            if (valid) {
                int leader = __ffs(m) - 1;
                if (lane == leader)
                    atomicAdd(&s_hist[b0], 2u * (unsigned)__popc(m));
            }
        }
    }
    // direct tile
    #pragma unroll
    for (int u = 0; u < 4; u++) {
        float4 o = make_float4(acc[u][0], acc[u][1], acc[u][2], acc[u][3]);
        *(float4*)&g_G[(size_t)(i0 + ty * 4 + u) * 4096 + j0 + tx * 4] = o;
    }
    // mirror tile via smem transpose
    #pragma unroll
    for (int u = 0; u < 4; u++)
        #pragma unroll
        for (int v = 0; v < 4; v++)
            Ts[tx * 4 + v][ty * 4 + u] = acc[u][v];
    __syncthreads();
    {
        int a = tid >> 2;
        int b0 = (tid & 3) * 16;
        #pragma unroll
        for (int q = 0; q < 4; q++) {
            float4 o = *(const float4*)&Ts[a][b0 + q * 4];
            *(float4*)&g_G[(size_t)(j0 + a) * 4096 + i0 + b0 + q * 4] = o;
        }
    }
    unsigned hv = s_hist[tid];
    if (hv) atomicAdd(&g_hist[tid], hv);
}

// ---------------- prefix scan -> pick squared-distance cutoff ----------------
__global__ void k_scan() {
    __shared__ unsigned s_h[256];
    __shared__ int s_min;
    int k = threadIdx.x;
    s_h[k] = g_hist[k];
    if (k == 0) s_min = 256;
    __syncthreads();
    unsigned cnt = 0;
    for (int b = 0; b <= k; b++) cnt += s_h[b];
    if ((float)cnt >= 409.6f) atomicMin(&s_min, k);  // 0.1 * 4096
    __syncthreads();
    if (k == 0) {
        int kk = (s_min >= 256) ? 0 : s_min;
        g_cut = g_cuts[kk];
    }
}

// ---------------- dense agg = A @ h, deg, E (mask from G, no atomics) --------
__global__ __launch_bounds__(256) void k_agg() {
    __shared__ float h_s[128][51];
    __shared__ float sq_s[128];
    __shared__ float G_s[32][129];
    __shared__ unsigned s_E;
    int tid = threadIdx.x;
    if (tid == 0) s_E = 0u;
    int r = tid >> 3;
    int tx = tid & 7;
    int i = blockIdx.x * 32 + r;
    float cut = g_cut;
    float sqi = g_sq[i];
    float acc[7];
    #pragma unroll
    for (int u = 0; u < 7; u++) acc[u] = 0.0f;
    int deg = 0;
    for (int jt = 0; jt < 4096; jt += 128) {
        __syncthreads();
        for (int t = tid; t < 128 * 50; t += 256) {
            int rr = t / 50, c = t % 50;
            h_s[rr][c] = g_h[(size_t)(jt + rr) * 50 + c];
        }
        if (tid < 128) sq_s[tid] = g_sq[jt + tid];
        for (int t = tid; t < 32 * 128; t += 256) {
            int rr = t >> 7, jj = t & 127;
            G_s[rr][jj] = g_G[(size_t)(blockIdx.x * 32 + rr) * 4096 + jt + jj];
        }
        __syncthreads();
        #pragma unroll 4
        for (int jj = 0; jj < 128; jj++) {
            float g = G_s[r][jj];
            float dd = fmaxf(sqi - 2.0f * g + sq_s[jj], 0.0f);
            if (dd < cut && (jt + jj) != i) {
                deg++;
                #pragma unroll
                for (int u = 0; u < 7; u++) {
                    int c = tx + 8 * u;
                    if (c < 50) acc[u] += h_s[jj][c];
                }
            }
        }
    }
    #pragma unroll
    for (int u = 0; u < 7; u++) {
        int c = tx + 8 * u;
        if (c < 50) g_agg[(size_t)i * 50 + c] = acc[u];
    }
    if (tx == 0) {
        g_deg[i] = (float)deg;
        atomicAdd(&s_E, (unsigned)deg);
    }
    __syncthreads();
    if (tid == 0 && s_E) atomicAdd(&g_E, s_E);
}

// ---------------- Z = leaky((agg/deg) Wrel^T + brel + h Wroot^T) -------------
__global__ __launch_bounds__(256) void k_z(const float* __restrict__ wrel,
                                           const float* __restrict__ brel,
                                           const float* __restrict__ wroot) {
    __shared__ float s_m[16][52];
    __shared__ float s_h[16][52];
    __shared__ float w1t[50][52];
    __shared__ float w2t[50][52];
    __shared__ float s_b[50];
    int i0 = blockIdx.x * 16;
    int tid = threadIdx.x;
    if (tid < 50) s_b[tid] = brel[tid];
    for (int t = tid; t < 2500; t += 256) {
        int o = t / 50, c = t % 50;
        w1t[c][o] = wrel[t];
        w2t[c][o] = wroot[t];
    }
    for (int t = tid; t < 800; t += 256) {
        int r = t / 50, c = t % 50;
        float dg = fmaxf(g_deg[i0 + r], 1.0f);
        s_m[r][c] = g_agg[(size_t)(i0 + r) * 50 + c] / dg;
        s_h[r][c] = g_h[(size_t)(i0 + r) * 50 + c];
    }
    __syncthreads();
    for (int t = tid; t < 800; t += 256) {
        int r = t / 50, o = t % 50;
        float a = s_b[o];
        #pragma unroll
        for (int c = 0; c < 50; c++)
            a = fmaf(s_m[r][c], w1t[c][o], fmaf(s_h[r][c], w2t[c][o], a));
        float z = (a >= 0.0f) ? a : 0.01f * a;
        g_Z[(size_t)(i0 + r) * 50 + o] = z;
    }
}

// ---------------- column sums of Z (softmax over size-1 axis == ones) --------
__global__ __launch_bounds__(256) void k_colsum() {
    __shared__ float red[256];
    int c = blockIdx.x, tid = threadIdx.x;
    float s = 0.0f;
    for (int i = tid; i < 4096; i += 256) s += g_Z[(size_t)i * 50 + c];
    red[tid] = s;
    __syncthreads();
    for (int w = 128; w > 0; w >>= 1) {
        if (tid < w) red[tid] += red[tid + w];
        __syncthreads();
    }
    if (tid == 0) g_colsum[c] = red[0];
}

// ---------------- final head ----------------
__global__ void k_final(const float* __restrict__ wrel, const float* __restrict__ brel,
                        const float* __restrict__ wroot,
                        const float* __restrict__ l1w, const float* __restrict__ l1b,
                        const float* __restrict__ l2w, const float* __restrict__ l2b,
                        float* __restrict__ out, int out_size) {
    __shared__ float xp0[50];
    __shared__ float xp[50];
    __shared__ float v1[25];
    int tid = threadIdx.x;
    if (tid < 50) xp0[tid] = g_colsum[tid];
    __syncthreads();
    float Ef = (float)g_E;
    float degv = fmaxf(Ef, 1.0f);
    if (tid < 50) {
        float a = brel[tid];
        for (int c = 0; c < 50; c++) {
            float m = (Ef * xp0[c]) / degv;
            a = fmaf(m, wrel[tid * 50 + c], fmaf(xp0[c], wroot[tid * 50 + c], a));
        }
        xp[tid] = (a >= 0.0f) ? a : 0.01f * a;
    }
    __syncthreads();
    if (tid < 25) {
        float a = l1b[tid];
        for (int c = 0; c < 50; c++) a = fmaf(xp[c], l1w[tid * 50 + c], a);
        v1[tid] = (a >= 0.0f) ? a : 0.01f * a;
    }
    __syncthreads();
    if (tid == 0) {
        float v2[2];
        for (int k = 0; k < 2; k++) {
            float a = l2b[k];
            for (int c = 0; c < 25; c++) a = fmaf(v1[c], l2w[k * 25 + c], a);
            v2[k] = (a >= 0.0f) ? a : 0.01f * a;
        }
        float mx = fmaxf(v2[0], v2[1]);
        float e0 = expf(v2[0] - mx), e1 = expf(v2[1] - mx);
        float inv = 1.0f / (e0 + e1);
        float p0 = e0 * inv, p1 = e1 * inv;
        int am = (p1 > p0) ? 1 : 0;
        float pm = fmaxf(p0, p1);
        unsigned E = g_E;
        float l1 = sqrtf((float)(16777216u - E)) / 16777216.0f;
        if (out_size > 0) out[0] = pm;
        if (out_size > 1) out[1] = (float)am;
        if (out_size > 2) out[2] = l1;
    }
}

// ---------------- launch ----------------
extern "C" void kernel_launch(void* const* d_in, const int* in_sizes, int n_in,
                              void* d_out, int out_size) {
    (void)in_sizes; (void)n_in;
    const float* x        = (const float*)d_in[0];
    const float* conv1_w  = (const float*)d_in[1];
    const float* conv1_b  = (const float*)d_in[2];
    const float* conv2_w  = (const float*)d_in[3];
    const float* conv2_b  = (const float*)d_in[4];
    const float* fc_w     = (const float*)d_in[5];
    const float* fc_b     = (const float*)d_in[6];
    const float* erel_w   = (const float*)d_in[7];
    const float* erel_b   = (const float*)d_in[8];
    const float* eroot_w  = (const float*)d_in[9];
    // d_in[10..14]: pool_* / mlp_* — dead (softmax over size-1 axis == 1)
    const float* lin1_w   = (const float*)d_in[15];
    const float* lin1_b   = (const float*)d_in[16];
    const float* lin2_w   = (const float*)d_in[17];
    const float* lin2_b   = (const float*)d_in[18];
    float* out = (float*)d_out;

    const int SMEM2 = (512 + 2 * 4352) * 4;   // 36928 B
    k_prep<<<253, 256>>>(conv2_w);
    k_conv1<<<4096, 256>>>(x, conv1_w, conv1_b);
    k_conv2<<<2048, 256, SMEM2>>>(conv2_b);
    k_fc<<<512, 128>>>(fc_w, fc_b);
    k_sq<<<16, 256>>>();
    k_gram<<<dim3(64, 64), 256>>>();
    k_scan<<<1, 256>>>();
    k_agg<<<128, 256>>>();
    k_z<<<256, 256>>>(erel_w, erel_b, eroot_w);
    k_colsum<<<50, 256>>>();
    k_final<<<1, 64>>>(erel_w, erel_b, eroot_w, lin1_w, lin1_b, lin2_w, lin2_b, out, out_size);
}